// round 2
// baseline (speedup 1.0000x reference)
#include <cuda_runtime.h>
#include <math.h>

#define Nn    50000
#define Ee    800000
#define LGEe  1600000
#define FNODE 256
#define Tt    64
#define HIDd  128
#define OUTd  64
#define SLOPE 0.2f

typedef unsigned long long u64;
typedef unsigned int u32;

// ---------------- scratch (static device globals; no allocation) ----------------
__device__ float    B_deg_lg[Ee];
__device__ float    B_aggT[(size_t)Ee * Tt];
__device__ float    B_h1[(size_t)Ee * HIDd];
__device__ float    B_agg1[(size_t)Ee * HIDd];
__device__ float    B_h2[(size_t)Ee * HIDd];
__device__ float    B_deg_raw[Nn];
__device__ float    B_degN[Nn];
__device__ float    B_aggN[(size_t)Nn * HIDd];
__device__ float    B_tmp[(size_t)Nn * HIDd];
__device__ float    B_edge_repr[(size_t)Nn * HIDd];
__device__ float    B_aggr_edge[(size_t)Nn * HIDd];
__device__ float    B_xws[(size_t)Nn * HIDd];
__device__ float    B_xwn[(size_t)Nn * HIDd];
__device__ float    B_hn1[(size_t)Nn * HIDd];
__device__ float    B_hn2[(size_t)Nn * HIDd];
__device__ float    B_q[(size_t)Nn * HIDd];
__device__ float    B_k[(size_t)Nn * HIDd];
__device__ float    B_v[(size_t)Nn * HIDd];
__device__ float    B_attn[(size_t)Nn * HIDd];
__device__ float    B_score[Ee];
__device__ unsigned B_menc[Nn];
__device__ float    B_den[Nn];

// ---------------- small helpers ----------------
__device__ __forceinline__ unsigned flipf(float f) {
    unsigned u = __float_as_uint(f);
    unsigned mask = (u & 0x80000000u) ? 0xFFFFFFFFu : 0x80000000u;
    return u ^ mask;
}
__device__ __forceinline__ float unflipf(unsigned u) {
    unsigned mask = (u & 0x80000000u) ? 0x80000000u : 0xFFFFFFFFu;
    return __uint_as_float(u ^ mask);
}

// ---------------- zero fill ----------------
__global__ void zero_k(float* p, long n4) {
    long t = (long)blockIdx.x * blockDim.x + threadIdx.x;
    if (t < n4) ((float4*)p)[t] = make_float4(0.f, 0.f, 0.f, 0.f);
}

// ---------------- line-graph aggregation of et (T=64) + deg ----------------
__global__ void lg_agg64_k(const int* __restrict__ src, const int* __restrict__ dst,
                           const float* __restrict__ et, float* __restrict__ agg,
                           float* __restrict__ deg) {
    long t = (long)blockIdx.x * blockDim.x + threadIdx.x;
    int e = (int)(t >> 4), c = (int)(t & 15);
    if (e >= LGEe) return;
    int s = src[e], d = dst[e];
    float4 v = *(const float4*)(et + (size_t)s * Tt + c * 4);
    float* o = agg + (size_t)d * Tt + c * 4;
    atomicAdd(o + 0, v.x); atomicAdd(o + 1, v.y);
    atomicAdd(o + 2, v.z); atomicAdd(o + 3, v.w);
    if (c == 0) atomicAdd(deg + d, 1.0f);
}

// ---------------- generic 128-wide gather/scatter-add aggregation ----------------
__global__ void agg128_k(const int* __restrict__ src, const int* __restrict__ dst,
                         const float* __restrict__ h, float* __restrict__ agg, int nE) {
    long t = (long)blockIdx.x * blockDim.x + threadIdx.x;
    int e = (int)(t >> 5), c = (int)(t & 31);
    if (e >= nE) return;
    int s = src[e], d = dst[e];
    float4 v = *(const float4*)(h + (size_t)s * HIDd + c * 4);
    float* o = agg + (size_t)d * HIDd + c * 4;
    atomicAdd(o + 0, v.x); atomicAdd(o + 1, v.y);
    atomicAdd(o + 2, v.z); atomicAdd(o + 3, v.w);
}

// ---------------- edge->node scatter to both endpoints ----------------
__global__ void e2n_agg_k(const int* __restrict__ h0, const int* __restrict__ h1,
                          const float* __restrict__ h2, float* __restrict__ agg,
                          float* __restrict__ deg) {
    long t = (long)blockIdx.x * blockDim.x + threadIdx.x;
    int e = (int)(t >> 5), c = (int)(t & 31);
    if (e >= Ee) return;
    int a = h0[e], b = h1[e];
    float4 v = *(const float4*)(h2 + (size_t)e * HIDd + c * 4);
    float* oa = agg + (size_t)a * HIDd + c * 4;
    float* ob = agg + (size_t)b * HIDd + c * 4;
    atomicAdd(oa + 0, v.x); atomicAdd(oa + 1, v.y);
    atomicAdd(oa + 2, v.z); atomicAdd(oa + 3, v.w);
    atomicAdd(ob + 0, v.x); atomicAdd(ob + 1, v.y);
    atomicAdd(ob + 2, v.z); atomicAdd(ob + 3, v.w);
    if (c == 0) { atomicAdd(deg + a, 1.0f); atomicAdd(deg + b, 1.0f); }
}

// ---------------- degree count on raw graph ----------------
__global__ void deg_k(const int* __restrict__ dst, float* __restrict__ deg, int nE) {
    int e = blockIdx.x * blockDim.x + threadIdx.x;
    if (e < nE) atomicAdd(deg + dst[e], 1.0f);
}

// ---------------- o = relu(a + b/max(deg,1)) ----------------
__global__ void addrelu_scaled_k(const float* __restrict__ a, const float* __restrict__ b,
                                 const float* __restrict__ deg,
                                 float* __restrict__ o, long n4) {
    long t = (long)blockIdx.x * blockDim.x + threadIdx.x;
    if (t >= n4) return;
    long r = (t * 4) / HIDd;
    float inv = __fdividef(1.0f, fmaxf(deg[r], 1.0f));
    float4 va = ((const float4*)a)[t], vb = ((const float4*)b)[t];
    float4 rr;
    rr.x = fmaxf(va.x + vb.x * inv, 0.f); rr.y = fmaxf(va.y + vb.y * inv, 0.f);
    rr.z = fmaxf(va.z + vb.z * inv, 0.f); rr.w = fmaxf(va.w + vb.w * inv, 0.f);
    ((float4*)o)[t] = rr;
}

// ==================================================================================
// Packed-f32x2 SGEMM:  C[M x 128] = epi( [A0*rs0 | A1*rs1] @ [W0 ; W1] )
// 128x128 block tile, BK=16, 256 threads, 8x8 microtile, accumulators in f32x2.
// ==================================================================================
__device__ __forceinline__ float apply_epi(float v, int epi) {
    if (epi == 1) return fmaxf(v, 0.f);
    if (epi == 2) return v > 0.f ? v : SLOPE * v;
    return v;
}

__global__ void __launch_bounds__(256) gemm_k(
    const float* __restrict__ A0, int K0, const float* __restrict__ rs0,
    const float* __restrict__ W0,
    const float* __restrict__ A1, int K1, const float* __restrict__ rs1,
    const float* __restrict__ W1,
    float* __restrict__ C, int M, int epi)
{
    __shared__ float As2[16][256];   // A tile, k-major, each value duplicated {a,a}
    __shared__ float Bs[16][128];    // W tile, k-major
    const int tid = threadIdx.x;
    const int tx = tid & 15;         // col group (8 cols)
    const int ty = tid >> 4;         // row group (8 rows)
    const int bm = blockIdx.x * 128;

    u64 acc[8][4];
#pragma unroll
    for (int i = 0; i < 8; i++)
#pragma unroll
        for (int j = 0; j < 4; j++) acc[i][j] = 0ull;

    const int K = K0 + K1;
    for (int kc = 0; kc < K; kc += 16) {
        const bool first = (kc < K0);
        const float* A = first ? A0 : A1;
        const float* rs = first ? rs0 : rs1;
        const float* W = first ? W0 : W1;
        const int kb = first ? kc : kc - K0;
        const int lda = first ? K0 : K1;

        // ---- A tile: 128 rows x 16 k, store transposed + duplicated ----
#pragma unroll
        for (int i = 0; i < 2; i++) {
            int idx = tid * 2 + i;          // 0..511 float4 slots
            int row = idx >> 2;             // 0..127
            int c4 = (idx & 3) * 4;         // 0,4,8,12
            float4 v = make_float4(0.f, 0.f, 0.f, 0.f);
            int gr = bm + row;
            if (gr < M) {
                v = *(const float4*)(A + (size_t)gr * lda + kb + c4);
                if (rs) {
                    float s = __fdividef(1.0f, fmaxf(rs[gr], 1.0f));
                    v.x *= s; v.y *= s; v.z *= s; v.w *= s;
                }
            }
            *(float2*)&As2[c4 + 0][2 * row] = make_float2(v.x, v.x);
            *(float2*)&As2[c4 + 1][2 * row] = make_float2(v.y, v.y);
            *(float2*)&As2[c4 + 2][2 * row] = make_float2(v.z, v.z);
            *(float2*)&As2[c4 + 3][2 * row] = make_float2(v.w, v.w);
        }
        // ---- W tile: 16 x 128 ----
#pragma unroll
        for (int i = 0; i < 2; i++) {
            int idx = tid * 2 + i;          // 0..511 float4 slots
            int row = idx >> 5;
            int col = (idx & 31) * 4;
            *(float4*)&Bs[row][col] = *(const float4*)(W + (size_t)(kb + row) * 128 + col);
        }
        __syncthreads();

#pragma unroll
        for (int kk = 0; kk < 16; kk++) {
            u64 a2[8], b2[4];
            *(float4*)&a2[0] = *(const float4*)&As2[kk][16 * ty + 0];
            *(float4*)&a2[2] = *(const float4*)&As2[kk][16 * ty + 4];
            *(float4*)&a2[4] = *(const float4*)&As2[kk][16 * ty + 8];
            *(float4*)&a2[6] = *(const float4*)&As2[kk][16 * ty + 12];
            *(float4*)&b2[0] = *(const float4*)&Bs[kk][tx * 8 + 0];
            *(float4*)&b2[2] = *(const float4*)&Bs[kk][tx * 8 + 4];
#pragma unroll
            for (int i = 0; i < 8; i++)
#pragma unroll
                for (int j = 0; j < 4; j++)
                    asm("fma.rn.f32x2 %0, %1, %2, %0;"
                        : "+l"(acc[i][j]) : "l"(a2[i]), "l"(b2[j]));
        }
        __syncthreads();
    }

    // ---- epilogue ----
#pragma unroll
    for (int i = 0; i < 8; i++) {
        int gr = bm + ty * 8 + i;
        if (gr >= M) continue;
        float o[8];
#pragma unroll
        for (int j = 0; j < 4; j++) {
            u32 lo = (u32)(acc[i][j] & 0xFFFFFFFFull);
            u32 hi = (u32)(acc[i][j] >> 32);
            o[2 * j + 0] = apply_epi(__uint_as_float(lo), epi);
            o[2 * j + 1] = apply_epi(__uint_as_float(hi), epi);
        }
        float* crow = C + (size_t)gr * 128 + tx * 8;
        *(float4*)(crow + 0) = make_float4(o[0], o[1], o[2], o[3]);
        *(float4*)(crow + 4) = make_float4(o[4], o[5], o[6], o[7]);
    }
}

// ---------------- attention score + segment max ----------------
__global__ void score_k(const int* __restrict__ src, const int* __restrict__ dst,
                        const float* __restrict__ q, const float* __restrict__ kb,
                        float* __restrict__ score, unsigned* __restrict__ menc) {
    long t = (long)blockIdx.x * blockDim.x + threadIdx.x;
    int e = (int)(t >> 5), lane = (int)(t & 31);
    if (e >= Ee) return;
    int s = src[e], d = dst[e];
    float4 qv = *(const float4*)(q + (size_t)d * HIDd + lane * 4);
    float4 kv = *(const float4*)(kb + (size_t)s * HIDd + lane * 4);
    float p = qv.x * kv.x + qv.y * kv.y + qv.z * kv.z + qv.w * kv.w;
#pragma unroll
    for (int off = 16; off; off >>= 1) p += __shfl_xor_sync(0xffffffffu, p, off);
    if (lane == 0) {
        p *= 0.08838834764831845f;          // 1/sqrt(128)
        p = p > 0.f ? p : SLOPE * p;        // leaky relu
        score[e] = p;
        atomicMax(menc + d, flipf(p));
    }
}

// ---------------- exp(score - m) + segment sum ----------------
__global__ void ex_k(const int* __restrict__ dst, float* __restrict__ score,
                     const unsigned* __restrict__ menc, float* __restrict__ den) {
    int e = blockIdx.x * blockDim.x + threadIdx.x;
    if (e >= Ee) return;
    int d = dst[e];
    float m = unflipf(menc[d]);
    if (!isfinite(m)) m = 0.0f;
    float exv = expf(score[e] - m);
    score[e] = exv;
    atomicAdd(den + d, exv);
}

// ---------------- alpha * v[src] scatter ----------------
__global__ void attn_k(const int* __restrict__ src, const int* __restrict__ dst,
                       const float* __restrict__ score, const float* __restrict__ den,
                       const float* __restrict__ v, float* __restrict__ attn) {
    long t = (long)blockIdx.x * blockDim.x + threadIdx.x;
    int e = (int)(t >> 5), c = (int)(t & 31);
    if (e >= Ee) return;
    int s = src[e], d = dst[e];
    float alpha = score[e] / fmaxf(den[d], 1e-9f);
    float4 vv = *(const float4*)(v + (size_t)s * HIDd + c * 4);
    float* o = attn + (size_t)d * HIDd + c * 4;
    atomicAdd(o + 0, alpha * vv.x); atomicAdd(o + 1, alpha * vv.y);
    atomicAdd(o + 2, alpha * vv.z); atomicAdd(o + 3, alpha * vv.w);
}

// ---------------- final: logits = (hn2+attn) @ W_out[128x64]; log_softmax ----------------
__global__ void __launch_bounds__(256) final_k(const float* __restrict__ hn2,
                                               const float* __restrict__ attn,
                                               const float* __restrict__ Wout,
                                               float* __restrict__ out) {
    __shared__ float sW[128 * 64];
    __shared__ float srow[8][128];
    int tid = threadIdx.x;
#pragma unroll
    for (int i = 0; i < 32; i++) sW[tid + i * 256] = Wout[tid + i * 256];
    __syncthreads();

    int w = tid >> 5, lane = tid & 31;
    int n = blockIdx.x * 8 + w;
    if (n >= Nn) return;

    float4 a = *(const float4*)(hn2 + (size_t)n * 128 + lane * 4);
    float4 b = *(const float4*)(attn + (size_t)n * 128 + lane * 4);
    float4 r = make_float4(a.x + b.x, a.y + b.y, a.z + b.z, a.w + b.w);
    *(float4*)&srow[w][lane * 4] = r;
    __syncwarp();

    float acc0 = 0.f, acc1 = 0.f;
#pragma unroll 8
    for (int k = 0; k < 128; k++) {
        float rv = srow[w][k];
        acc0 += rv * sW[k * 64 + lane];
        acc1 += rv * sW[k * 64 + lane + 32];
    }
    float mx = fmaxf(acc0, acc1);
#pragma unroll
    for (int off = 16; off; off >>= 1) mx = fmaxf(mx, __shfl_xor_sync(0xffffffffu, mx, off));
    float sm = expf(acc0 - mx) + expf(acc1 - mx);
#pragma unroll
    for (int off = 16; off; off >>= 1) sm += __shfl_xor_sync(0xffffffffu, sm, off);
    float ls = logf(sm);
    out[(size_t)n * 64 + lane] = acc0 - mx - ls;
    out[(size_t)n * 64 + lane + 32] = acc1 - mx - ls;
}

// ---------------- host ----------------
#define SYMADDR(p, s) do { void* _t = nullptr; cudaGetSymbolAddress(&_t, s); (p) = (decltype(p))_t; } while (0)

static inline void zero_buf(float* p, size_t nfloats) {
    long n4 = (long)(nfloats / 4);
    zero_k<<<(int)((n4 + 255) / 256), 256>>>(p, n4);
}

extern "C" void kernel_launch(void* const* d_in, const int* in_sizes, int n_in,
                              void* d_out, int out_size) {
    const float* x   = (const float*)d_in[0];
    const float* et  = (const float*)d_in[1];
    const int*   H   = (const int*)d_in[2];
    const int*   rei = (const int*)d_in[3];
    const int*   lg  = (const int*)d_in[4];
    const float* W_tsa1_s = (const float*)d_in[5];
    const float* W_tsa1_n = (const float*)d_in[6];
    const float* W_tsa2_s = (const float*)d_in[7];
    const float* W_tsa2_n = (const float*)d_in[8];
    const float* W_etn    = (const float*)d_in[9];
    const float* W_eg_lin = (const float*)d_in[10];
    const float* W_ea_s   = (const float*)d_in[11];
    const float* W_ea_n   = (const float*)d_in[12];
    const float* W_an1_s  = (const float*)d_in[13];
    const float* W_an1_n  = (const float*)d_in[14];
    const float* W_an2_s  = (const float*)d_in[15];
    const float* W_an2_n  = (const float*)d_in[16];
    const float* Wq       = (const float*)d_in[17];
    const float* Wk       = (const float*)d_in[18];
    const float* Wv       = (const float*)d_in[19];
    const float* W_out    = (const float*)d_in[20];
    float* out = (float*)d_out;

    const int* H0 = H,        * H1 = H + Ee;
    const int* rsrc = rei,    * rdst = rei + Ee;
    const int* lsrc = lg,     * ldst = lg + LGEe;

    float *b_deg_lg, *b_aggT, *b_h1, *b_agg1, *b_h2, *b_deg_raw, *b_degN, *b_aggN,
          *b_tmp, *b_edge_repr, *b_aggr_edge, *b_xws, *b_xwn, *b_hn1, *b_hn2,
          *b_q, *b_k, *b_v, *b_attn, *b_score, *b_den;
    unsigned* b_menc;
    SYMADDR(b_deg_lg, B_deg_lg);   SYMADDR(b_aggT, B_aggT);
    SYMADDR(b_h1, B_h1);           SYMADDR(b_agg1, B_agg1);
    SYMADDR(b_h2, B_h2);           SYMADDR(b_deg_raw, B_deg_raw);
    SYMADDR(b_degN, B_degN);       SYMADDR(b_aggN, B_aggN);
    SYMADDR(b_tmp, B_tmp);         SYMADDR(b_edge_repr, B_edge_repr);
    SYMADDR(b_aggr_edge, B_aggr_edge);
    SYMADDR(b_xws, B_xws);         SYMADDR(b_xwn, B_xwn);
    SYMADDR(b_hn1, B_hn1);         SYMADDR(b_hn2, B_hn2);
    SYMADDR(b_q, B_q);             SYMADDR(b_k, B_k);
    SYMADDR(b_v, B_v);             SYMADDR(b_attn, B_attn);
    SYMADDR(b_score, B_score);     SYMADDR(b_menc, B_menc);
    SYMADDR(b_den, B_den);

    const int TB = 256;
    const int gridE_gemm = (Ee + 127) / 128;
    const int gridN_gemm = (Nn + 127) / 128;

    // ---- TSA layer 1 on line graph ----
    zero_buf(b_aggT, (size_t)Ee * Tt);
    zero_buf(b_deg_lg, Ee);
    lg_agg64_k<<<(int)(((long)LGEe * 16 + TB - 1) / TB), TB>>>(lsrc, ldst, et, b_aggT, b_deg_lg);
    gemm_k<<<gridE_gemm, 256>>>(et, Tt, nullptr, W_tsa1_s,
                                b_aggT, Tt, b_deg_lg, W_tsa1_n, b_h1, Ee, 1 /*relu*/);

    // ---- TSA layer 2 on line graph ----
    zero_buf(b_agg1, (size_t)Ee * HIDd);
    agg128_k<<<(int)(((long)LGEe * 32 + TB - 1) / TB), TB>>>(lsrc, ldst, b_h1, b_agg1, LGEe);
    gemm_k<<<gridE_gemm, 256>>>(b_h1, HIDd, nullptr, W_tsa2_s,
                                b_agg1, HIDd, b_deg_lg, W_tsa2_n, b_h2, Ee, 0);

    // ---- EdgeToNodeConv + EdgeGCN linear ----
    zero_buf(b_aggN, (size_t)Nn * HIDd);
    zero_buf(b_degN, Nn);
    e2n_agg_k<<<(int)(((long)Ee * 32 + TB - 1) / TB), TB>>>(H0, H1, b_h2, b_aggN, b_degN);
    gemm_k<<<gridN_gemm, 256>>>(b_aggN, HIDd, b_degN, W_etn,
                                nullptr, 0, nullptr, nullptr, b_tmp, Nn, 2 /*leaky*/);
    gemm_k<<<gridN_gemm, 256>>>(b_tmp, HIDd, nullptr, W_eg_lin,
                                nullptr, 0, nullptr, nullptr, b_edge_repr, Nn, 0);

    // ---- raw-graph degree ----
    zero_buf(b_deg_raw, Nn);
    deg_k<<<(Ee + TB - 1) / TB, TB>>>(rdst, b_deg_raw, Ee);

    // ---- edge_aggr SAGE ----
    zero_buf(b_aggN, (size_t)Nn * HIDd);
    agg128_k<<<(int)(((long)Ee * 32 + TB - 1) / TB), TB>>>(rsrc, rdst, b_edge_repr, b_aggN, Ee);
    gemm_k<<<gridN_gemm, 256>>>(b_edge_repr, HIDd, nullptr, W_ea_s,
                                b_aggN, HIDd, b_deg_raw, W_ea_n, b_aggr_edge, Nn, 0);

    // ---- attr_node_model layer 1 (transform-first: mean is linear) ----
    gemm_k<<<gridN_gemm, 256>>>(x, FNODE, nullptr, W_an1_s,
                                nullptr, 0, nullptr, nullptr, b_xws, Nn, 0);
    gemm_k<<<gridN_gemm, 256>>>(x, FNODE, nullptr, W_an1_n,
                                nullptr, 0, nullptr, nullptr, b_xwn, Nn, 0);
    zero_buf(b_aggN, (size_t)Nn * HIDd);
    agg128_k<<<(int)(((long)Ee * 32 + TB - 1) / TB), TB>>>(rsrc, rdst, b_xwn, b_aggN, Ee);
    addrelu_scaled_k<<<(int)(((long)Nn * HIDd / 4 + TB - 1) / TB), TB>>>(
        b_xws, b_aggN, b_deg_raw, b_hn1, (long)Nn * HIDd / 4);

    // ---- attr_node_model layer 2 ----
    zero_buf(b_aggN, (size_t)Nn * HIDd);
    agg128_k<<<(int)(((long)Ee * 32 + TB - 1) / TB), TB>>>(rsrc, rdst, b_hn1, b_aggN, Ee);
    gemm_k<<<gridN_gemm, 256>>>(b_hn1, HIDd, nullptr, W_an2_s,
                                b_aggN, HIDd, b_deg_raw, W_an2_n, b_hn2, Nn, 0);

    // ---- MixAttention projections ----
    gemm_k<<<gridN_gemm, 256>>>(b_hn2, HIDd, nullptr, Wq,
                                nullptr, 0, nullptr, nullptr, b_q, Nn, 0);
    gemm_k<<<gridN_gemm, 256>>>(b_aggr_edge, HIDd, nullptr, Wk,
                                nullptr, 0, nullptr, nullptr, b_k, Nn, 0);
    gemm_k<<<gridN_gemm, 256>>>(b_aggr_edge, HIDd, nullptr, Wv,
                                nullptr, 0, nullptr, nullptr, b_v, Nn, 0);

    // ---- attention softmax over incoming edges ----
    zero_buf((float*)b_menc, Nn);   // 0 decodes to NaN -> treated as -inf/empty
    zero_buf(b_den, Nn);
    zero_buf(b_attn, (size_t)Nn * HIDd);
    score_k<<<(int)(((long)Ee * 32 + TB - 1) / TB), TB>>>(rsrc, rdst, b_q, b_k, b_score, b_menc);
    ex_k<<<(Ee + TB - 1) / TB, TB>>>(rdst, b_score, b_menc, b_den);
    attn_k<<<(int)(((long)Ee * 32 + TB - 1) / TB), TB>>>(rsrc, rdst, b_score, b_den, b_v, b_attn);

    // ---- classifier + log_softmax ----
    final_k<<<(Nn + 7) / 8, 256>>>(b_hn2, b_attn, W_out, out);
}

// round 3
// speedup vs baseline: 1.3095x; 1.3095x over previous
#include <cuda_runtime.h>
#include <math.h>

#define Nn    50000
#define Ee    800000
#define LGEe  1600000
#define FNODE 256
#define Tt    64
#define HIDd  128
#define OUTd  64
#define SLOPE 0.2f

typedef unsigned long long u64;
typedef unsigned int u32;

// ---------------- scratch (static device globals; no allocation) ----------------
__device__ float    B_aggT[(size_t)Ee * Tt];
__device__ float    B_h1[(size_t)Ee * HIDd];
__device__ float    B_agg1[(size_t)Ee * HIDd];
__device__ float    B_h2[(size_t)Ee * HIDd];
__device__ float    B_aggN[(size_t)Nn * HIDd];
__device__ float    B_tmp[(size_t)Nn * HIDd];
__device__ float    B_edge_repr[(size_t)Nn * HIDd];
__device__ float    B_aggr_edge[(size_t)Nn * HIDd];
__device__ float    B_xws[(size_t)Nn * HIDd];
__device__ float    B_xwn[(size_t)Nn * HIDd];
__device__ float    B_hn1[(size_t)Nn * HIDd];
__device__ float    B_hn2[(size_t)Nn * HIDd];
__device__ float    B_q[(size_t)Nn * HIDd];
__device__ float    B_k[(size_t)Nn * HIDd];
__device__ float    B_v[(size_t)Nn * HIDd];
__device__ float    B_attn[(size_t)Nn * HIDd];
__device__ float    B_score[Ee];

// CSR structures
__device__ int CSR_cnt[Ee];      // reused count buffer (max #rows = Ee)
__device__ int CSR_cur[Ee];      // reused cursor buffer
__device__ int LG_rp[Ee + 1];
__device__ int LG_col[LGEe];
__device__ int RAW_rp[Nn + 1];
__device__ int RAW_col[Ee];
__device__ int H_rp[Nn + 1];
__device__ int H_col[2 * Ee];

// ================= CSR build kernels =================
__global__ void zero_int_k(int* p, int n) {
    int t = blockIdx.x * blockDim.x + threadIdx.x;
    if (t < n) p[t] = 0;
}
__global__ void hist_k(const int* __restrict__ d, int* __restrict__ cnt, int nE) {
    int e = blockIdx.x * blockDim.x + threadIdx.x;
    if (e < nE) atomicAdd(cnt + d[e], 1);
}
// single-block exclusive scan: rp[i] = sum cnt[0..i-1]; rp[n] = total
__global__ void __launch_bounds__(1024) scan_k(const int* __restrict__ cnt, int n,
                                               int* __restrict__ rp) {
    __shared__ int wsum[32];
    __shared__ int s_carry;
    int tid = threadIdx.x;
    int lane = tid & 31, wid = tid >> 5;
    if (tid == 0) s_carry = 0;
    __syncthreads();
    for (int base = 0; base < n; base += 4096) {
        int idx = base + tid * 4;
        int v0 = 0, v1 = 0, v2 = 0, v3 = 0;
        if (idx + 3 < n) {
            int4 c = *(const int4*)(cnt + idx);
            v0 = c.x; v1 = c.y; v2 = c.z; v3 = c.w;
        } else {
            if (idx + 0 < n) v0 = cnt[idx + 0];
            if (idx + 1 < n) v1 = cnt[idx + 1];
            if (idx + 2 < n) v2 = cnt[idx + 2];
        }
        int s = v0 + v1 + v2 + v3;
        int inc = s;
#pragma unroll
        for (int o = 1; o < 32; o <<= 1) {
            int t = __shfl_up_sync(0xffffffffu, inc, o);
            if (lane >= o) inc += t;
        }
        if (lane == 31) wsum[wid] = inc;
        __syncthreads();
        if (wid == 0) {
            int w = wsum[lane];
            int wi = w;
#pragma unroll
            for (int o = 1; o < 32; o <<= 1) {
                int t = __shfl_up_sync(0xffffffffu, wi, o);
                if (lane >= o) wi += t;
            }
            wsum[lane] = wi - w;   // exclusive
        }
        __syncthreads();
        int excl = s_carry + wsum[wid] + (inc - s);
        if (idx < n)     rp[idx]     = excl;
        if (idx + 1 < n) rp[idx + 1] = excl + v0;
        if (idx + 2 < n) rp[idx + 2] = excl + v0 + v1;
        if (idx + 3 < n) rp[idx + 3] = excl + v0 + v1 + v2;
        __syncthreads();                       // everyone done reading s_carry
        if (tid == 1023) s_carry = excl + s;   // running total
        __syncthreads();
    }
    if (tid == 0) rp[n] = s_carry;
}
__global__ void copy_int_k(const int* __restrict__ a, int* __restrict__ b, int n) {
    int t = blockIdx.x * blockDim.x + threadIdx.x;
    if (t < n) b[t] = a[t];
}
// fill with payload = src[e]
__global__ void fill_src_k(const int* __restrict__ dst, const int* __restrict__ src,
                           int* __restrict__ cur, int* __restrict__ col, int nE) {
    int e = blockIdx.x * blockDim.x + threadIdx.x;
    if (e >= nE) return;
    int p = atomicAdd(cur + dst[e], 1);
    col[p] = src[e];
}
// fill for H (2E entries), payload = edge id
__global__ void fill_eid2_k(const int* __restrict__ H, int* __restrict__ cur,
                            int* __restrict__ col, int nE) {
    int j = blockIdx.x * blockDim.x + threadIdx.x;
    if (j >= 2 * nE) return;
    int d = H[j];
    int e = (j < nE) ? j : j - nE;
    int p = atomicAdd(cur + d, 1);
    col[p] = e;
}

// ================= gather-based segment means =================
__global__ void gather64_k(const float* __restrict__ h, const int* __restrict__ rp,
                           const int* __restrict__ col, float* __restrict__ out, int nRows) {
    int warp = blockIdx.x * (blockDim.x >> 5) + (threadIdx.x >> 5);
    int lane = threadIdx.x & 31;
    if (warp >= nRows) return;
    int a = rp[warp], b = rp[warp + 1];
    float2 acc = make_float2(0.f, 0.f);
    for (int i = a; i < b; i++) {
        int s = __ldg(col + i);
        float2 v = *(const float2*)(h + (size_t)s * Tt + lane * 2);
        acc.x += v.x; acc.y += v.y;
    }
    float inv = __fdividef(1.f, fmaxf((float)(b - a), 1.f));
    acc.x *= inv; acc.y *= inv;
    *(float2*)(out + (size_t)warp * Tt + lane * 2) = acc;
}

__global__ void gather128_k(const float* __restrict__ h, const int* __restrict__ rp,
                            const int* __restrict__ col, float* __restrict__ out,
                            const float* __restrict__ addIn, int epi, int nRows) {
    int warp = blockIdx.x * (blockDim.x >> 5) + (threadIdx.x >> 5);
    int lane = threadIdx.x & 31;
    if (warp >= nRows) return;
    int a = rp[warp], b = rp[warp + 1];
    float4 acc = make_float4(0.f, 0.f, 0.f, 0.f);
    for (int i = a; i < b; i++) {
        int s = __ldg(col + i);
        float4 v = *(const float4*)(h + (size_t)s * HIDd + lane * 4);
        acc.x += v.x; acc.y += v.y; acc.z += v.z; acc.w += v.w;
    }
    float inv = __fdividef(1.f, fmaxf((float)(b - a), 1.f));
    acc.x *= inv; acc.y *= inv; acc.z *= inv; acc.w *= inv;
    if (addIn) {
        float4 w = *(const float4*)(addIn + (size_t)warp * HIDd + lane * 4);
        acc.x += w.x; acc.y += w.y; acc.z += w.z; acc.w += w.w;
    }
    if (epi == 1) {
        acc.x = fmaxf(acc.x, 0.f); acc.y = fmaxf(acc.y, 0.f);
        acc.z = fmaxf(acc.z, 0.f); acc.w = fmaxf(acc.w, 0.f);
    }
    *(float4*)(out + (size_t)warp * HIDd + lane * 4) = acc;
}

// ================= fused attention: score + softmax + weighted sum =================
__global__ void attn_fused_k(const float* __restrict__ q, const float* __restrict__ kk,
                             const float* __restrict__ v, const int* __restrict__ rp,
                             const int* __restrict__ col, float* __restrict__ sc,
                             float* __restrict__ attnOut, int nRows) {
    int warp = blockIdx.x * (blockDim.x >> 5) + (threadIdx.x >> 5);
    int lane = threadIdx.x & 31;
    if (warp >= nRows) return;
    int a = rp[warp], b = rp[warp + 1];
    float4 qv = *(const float4*)(q + (size_t)warp * HIDd + lane * 4);

    // pass 1: scores + max
    float m = -INFINITY;
    for (int i = a; i < b; i++) {
        int s = __ldg(col + i);
        float4 kv = *(const float4*)(kk + (size_t)s * HIDd + lane * 4);
        float p = qv.x * kv.x + qv.y * kv.y + qv.z * kv.z + qv.w * kv.w;
#pragma unroll
        for (int off = 16; off; off >>= 1) p += __shfl_xor_sync(0xffffffffu, p, off);
        p *= 0.08838834764831845f;          // 1/sqrt(128)
        p = p > 0.f ? p : SLOPE * p;        // leaky relu
        if (lane == 0) sc[i] = p;
        m = fmaxf(m, p);
    }
    __syncwarp();

    // pass 2: denominator
    float den = 0.f;
    for (int i = a + lane; i < b; i += 32) den += expf(sc[i] - m);
#pragma unroll
    for (int off = 16; off; off >>= 1) den += __shfl_xor_sync(0xffffffffu, den, off);
    den = fmaxf(den, 1e-9f);

    // pass 3: weighted sum of v
    float4 acc = make_float4(0.f, 0.f, 0.f, 0.f);
    for (int i = a; i < b; i++) {
        float alpha = expf(sc[i] - m) / den;
        int s = __ldg(col + i);
        float4 vv = *(const float4*)(v + (size_t)s * HIDd + lane * 4);
        acc.x += alpha * vv.x; acc.y += alpha * vv.y;
        acc.z += alpha * vv.z; acc.w += alpha * vv.w;
    }
    *(float4*)(attnOut + (size_t)warp * HIDd + lane * 4) = acc;
}

// ==================================================================================
// Packed-f32x2 SGEMM:  C[M x 128] = epi( [A0 | A1] @ [W0 ; W1] )   (at FFMA2 ceiling)
// ==================================================================================
__device__ __forceinline__ float apply_epi(float v, int epi) {
    if (epi == 1) return fmaxf(v, 0.f);
    if (epi == 2) return v > 0.f ? v : SLOPE * v;
    return v;
}

__global__ void __launch_bounds__(256) gemm_k(
    const float* __restrict__ A0, int K0, const float* __restrict__ W0,
    const float* __restrict__ A1, int K1, const float* __restrict__ W1,
    float* __restrict__ C, int M, int epi)
{
    __shared__ float As2[16][256];   // A tile, k-major, each value duplicated {a,a}
    __shared__ float Bs[16][128];    // W tile, k-major
    const int tid = threadIdx.x;
    const int tx = tid & 15;
    const int ty = tid >> 4;
    const int bm = blockIdx.x * 128;

    u64 acc[8][4];
#pragma unroll
    for (int i = 0; i < 8; i++)
#pragma unroll
        for (int j = 0; j < 4; j++) acc[i][j] = 0ull;

    const int K = K0 + K1;
    for (int kc = 0; kc < K; kc += 16) {
        const bool first = (kc < K0);
        const float* A = first ? A0 : A1;
        const float* W = first ? W0 : W1;
        const int kb = first ? kc : kc - K0;
        const int lda = first ? K0 : K1;

#pragma unroll
        for (int i = 0; i < 2; i++) {
            int idx = tid * 2 + i;
            int row = idx >> 2;
            int c4 = (idx & 3) * 4;
            float4 v = make_float4(0.f, 0.f, 0.f, 0.f);
            int gr = bm + row;
            if (gr < M) v = *(const float4*)(A + (size_t)gr * lda + kb + c4);
            *(float2*)&As2[c4 + 0][2 * row] = make_float2(v.x, v.x);
            *(float2*)&As2[c4 + 1][2 * row] = make_float2(v.y, v.y);
            *(float2*)&As2[c4 + 2][2 * row] = make_float2(v.z, v.z);
            *(float2*)&As2[c4 + 3][2 * row] = make_float2(v.w, v.w);
        }
#pragma unroll
        for (int i = 0; i < 2; i++) {
            int idx = tid * 2 + i;
            int row = idx >> 5;
            int col = (idx & 31) * 4;
            *(float4*)&Bs[row][col] = *(const float4*)(W + (size_t)(kb + row) * 128 + col);
        }
        __syncthreads();

#pragma unroll
        for (int kk = 0; kk < 16; kk++) {
            u64 a2[8], b2[4];
            *(float4*)&a2[0] = *(const float4*)&As2[kk][16 * ty + 0];
            *(float4*)&a2[2] = *(const float4*)&As2[kk][16 * ty + 4];
            *(float4*)&a2[4] = *(const float4*)&As2[kk][16 * ty + 8];
            *(float4*)&a2[6] = *(const float4*)&As2[kk][16 * ty + 12];
            *(float4*)&b2[0] = *(const float4*)&Bs[kk][tx * 8 + 0];
            *(float4*)&b2[2] = *(const float4*)&Bs[kk][tx * 8 + 4];
#pragma unroll
            for (int i = 0; i < 8; i++)
#pragma unroll
                for (int j = 0; j < 4; j++)
                    asm("fma.rn.f32x2 %0, %1, %2, %0;"
                        : "+l"(acc[i][j]) : "l"(a2[i]), "l"(b2[j]));
        }
        __syncthreads();
    }

#pragma unroll
    for (int i = 0; i < 8; i++) {
        int gr = bm + ty * 8 + i;
        if (gr >= M) continue;
        float o[8];
#pragma unroll
        for (int j = 0; j < 4; j++) {
            u32 lo = (u32)(acc[i][j] & 0xFFFFFFFFull);
            u32 hi = (u32)(acc[i][j] >> 32);
            o[2 * j + 0] = apply_epi(__uint_as_float(lo), epi);
            o[2 * j + 1] = apply_epi(__uint_as_float(hi), epi);
        }
        float* crow = C + (size_t)gr * 128 + tx * 8;
        *(float4*)(crow + 0) = make_float4(o[0], o[1], o[2], o[3]);
        *(float4*)(crow + 4) = make_float4(o[4], o[5], o[6], o[7]);
    }
}

// ---------------- final: logits = (hn2+attn) @ W_out[128x64]; log_softmax ----------------
__global__ void __launch_bounds__(256) final_k(const float* __restrict__ hn2,
                                               const float* __restrict__ attn,
                                               const float* __restrict__ Wout,
                                               float* __restrict__ out) {
    __shared__ float sW[128 * 64];
    __shared__ float srow[8][128];
    int tid = threadIdx.x;
#pragma unroll
    for (int i = 0; i < 32; i++) sW[tid + i * 256] = Wout[tid + i * 256];
    __syncthreads();

    int w = tid >> 5, lane = tid & 31;
    int n = blockIdx.x * 8 + w;
    if (n >= Nn) return;

    float4 a = *(const float4*)(hn2 + (size_t)n * 128 + lane * 4);
    float4 b = *(const float4*)(attn + (size_t)n * 128 + lane * 4);
    float4 r = make_float4(a.x + b.x, a.y + b.y, a.z + b.z, a.w + b.w);
    *(float4*)&srow[w][lane * 4] = r;
    __syncwarp();

    float acc0 = 0.f, acc1 = 0.f;
#pragma unroll 8
    for (int k = 0; k < 128; k++) {
        float rv = srow[w][k];
        acc0 += rv * sW[k * 64 + lane];
        acc1 += rv * sW[k * 64 + lane + 32];
    }
    float mx = fmaxf(acc0, acc1);
#pragma unroll
    for (int off = 16; off; off >>= 1) mx = fmaxf(mx, __shfl_xor_sync(0xffffffffu, mx, off));
    float sm = expf(acc0 - mx) + expf(acc1 - mx);
#pragma unroll
    for (int off = 16; off; off >>= 1) sm += __shfl_xor_sync(0xffffffffu, sm, off);
    float ls = logf(sm);
    out[(size_t)n * 64 + lane] = acc0 - mx - ls;
    out[(size_t)n * 64 + lane + 32] = acc1 - mx - ls;
}

// ---------------- host ----------------
#define SYMADDR(p, s) do { void* _t = nullptr; cudaGetSymbolAddress(&_t, s); (p) = (decltype(p))_t; } while (0)

extern "C" void kernel_launch(void* const* d_in, const int* in_sizes, int n_in,
                              void* d_out, int out_size) {
    const float* x   = (const float*)d_in[0];
    const float* et  = (const float*)d_in[1];
    const int*   H   = (const int*)d_in[2];
    const int*   rei = (const int*)d_in[3];
    const int*   lg  = (const int*)d_in[4];
    const float* W_tsa1_s = (const float*)d_in[5];
    const float* W_tsa1_n = (const float*)d_in[6];
    const float* W_tsa2_s = (const float*)d_in[7];
    const float* W_tsa2_n = (const float*)d_in[8];
    const float* W_etn    = (const float*)d_in[9];
    const float* W_eg_lin = (const float*)d_in[10];
    const float* W_ea_s   = (const float*)d_in[11];
    const float* W_ea_n   = (const float*)d_in[12];
    const float* W_an1_s  = (const float*)d_in[13];
    const float* W_an1_n  = (const float*)d_in[14];
    const float* W_an2_s  = (const float*)d_in[15];
    const float* W_an2_n  = (const float*)d_in[16];
    const float* Wq       = (const float*)d_in[17];
    const float* Wk       = (const float*)d_in[18];
    const float* Wv       = (const float*)d_in[19];
    const float* W_out    = (const float*)d_in[20];
    float* out = (float*)d_out;

    const int* rsrc = rei,    * rdst = rei + Ee;
    const int* lsrc = lg,     * ldst = lg + LGEe;

    float *b_aggT, *b_h1, *b_agg1, *b_h2, *b_aggN, *b_tmp, *b_edge_repr, *b_aggr_edge,
          *b_xws, *b_xwn, *b_hn1, *b_hn2, *b_q, *b_k, *b_v, *b_attn, *b_score;
    int *csr_cnt, *csr_cur, *lg_rp, *lg_col, *raw_rp, *raw_col, *h_rp, *h_col;
    SYMADDR(b_aggT, B_aggT);       SYMADDR(b_h1, B_h1);
    SYMADDR(b_agg1, B_agg1);       SYMADDR(b_h2, B_h2);
    SYMADDR(b_aggN, B_aggN);       SYMADDR(b_tmp, B_tmp);
    SYMADDR(b_edge_repr, B_edge_repr); SYMADDR(b_aggr_edge, B_aggr_edge);
    SYMADDR(b_xws, B_xws);         SYMADDR(b_xwn, B_xwn);
    SYMADDR(b_hn1, B_hn1);         SYMADDR(b_hn2, B_hn2);
    SYMADDR(b_q, B_q);             SYMADDR(b_k, B_k);
    SYMADDR(b_v, B_v);             SYMADDR(b_attn, B_attn);
    SYMADDR(b_score, B_score);
    SYMADDR(csr_cnt, CSR_cnt);     SYMADDR(csr_cur, CSR_cur);
    SYMADDR(lg_rp, LG_rp);         SYMADDR(lg_col, LG_col);
    SYMADDR(raw_rp, RAW_rp);       SYMADDR(raw_col, RAW_col);
    SYMADDR(h_rp, H_rp);           SYMADDR(h_col, H_col);

    const int TB = 256;
    const int gridE_gemm = (Ee + 127) / 128;
    const int gridN_gemm = (Nn + 127) / 128;
    const int gridE_row = (Ee + 7) / 8;     // warp-per-row, 8 warps/block
    const int gridN_row = (Nn + 7) / 8;

    // ======== CSR builds ========
    // line graph (rows = E edge-nodes, entries = LGE)
    zero_int_k<<<(Ee + TB - 1) / TB, TB>>>(csr_cnt, Ee);
    hist_k<<<(LGEe + TB - 1) / TB, TB>>>(ldst, csr_cnt, LGEe);
    scan_k<<<1, 1024>>>(csr_cnt, Ee, lg_rp);
    copy_int_k<<<(Ee + TB - 1) / TB, TB>>>(lg_rp, csr_cur, Ee);
    fill_src_k<<<(LGEe + TB - 1) / TB, TB>>>(ldst, lsrc, csr_cur, lg_col, LGEe);
    // raw graph (rows = N, entries = E, payload = src)
    zero_int_k<<<(Nn + TB - 1) / TB, TB>>>(csr_cnt, Nn);
    hist_k<<<(Ee + TB - 1) / TB, TB>>>(rdst, csr_cnt, Ee);
    scan_k<<<1, 1024>>>(csr_cnt, Nn, raw_rp);
    copy_int_k<<<(Nn + TB - 1) / TB, TB>>>(raw_rp, csr_cur, Nn);
    fill_src_k<<<(Ee + TB - 1) / TB, TB>>>(rdst, rsrc, csr_cur, raw_col, Ee);
    // H incidence (rows = N, entries = 2E, payload = edge id)
    zero_int_k<<<(Nn + TB - 1) / TB, TB>>>(csr_cnt, Nn);
    hist_k<<<(2 * Ee + TB - 1) / TB, TB>>>(H, csr_cnt, 2 * Ee);
    scan_k<<<1, 1024>>>(csr_cnt, Nn, h_rp);
    copy_int_k<<<(Nn + TB - 1) / TB, TB>>>(h_rp, csr_cur, Nn);
    fill_eid2_k<<<(2 * Ee + TB - 1) / TB, TB>>>(H, csr_cur, h_col, Ee);

    // ======== TSA layer 1 on line graph ========
    gather64_k<<<gridE_row, TB>>>(et, lg_rp, lg_col, b_aggT, Ee);
    gemm_k<<<gridE_gemm, 256>>>(et, Tt, W_tsa1_s, b_aggT, Tt, W_tsa1_n, b_h1, Ee, 1);

    // ======== TSA layer 2 on line graph ========
    gather128_k<<<gridE_row, TB>>>(b_h1, lg_rp, lg_col, b_agg1, nullptr, 0, Ee);
    gemm_k<<<gridE_gemm, 256>>>(b_h1, HIDd, W_tsa2_s, b_agg1, HIDd, W_tsa2_n, b_h2, Ee, 0);

    // ======== EdgeToNodeConv + EdgeGCN linear ========
    gather128_k<<<gridN_row, TB>>>(b_h2, h_rp, h_col, b_aggN, nullptr, 0, Nn);
    gemm_k<<<gridN_gemm, 256>>>(b_aggN, HIDd, W_etn, nullptr, 0, nullptr, b_tmp, Nn, 2);
    gemm_k<<<gridN_gemm, 256>>>(b_tmp, HIDd, W_eg_lin, nullptr, 0, nullptr, b_edge_repr, Nn, 0);

    // ======== edge_aggr SAGE ========
    gather128_k<<<gridN_row, TB>>>(b_edge_repr, raw_rp, raw_col, b_aggN, nullptr, 0, Nn);
    gemm_k<<<gridN_gemm, 256>>>(b_edge_repr, HIDd, W_ea_s, b_aggN, HIDd, W_ea_n, b_aggr_edge, Nn, 0);

    // ======== attr_node_model layer 1 (transform-first; fused add+relu) ========
    gemm_k<<<gridN_gemm, 256>>>(x, FNODE, W_an1_s, nullptr, 0, nullptr, b_xws, Nn, 0);
    gemm_k<<<gridN_gemm, 256>>>(x, FNODE, W_an1_n, nullptr, 0, nullptr, b_xwn, Nn, 0);
    gather128_k<<<gridN_row, TB>>>(b_xwn, raw_rp, raw_col, b_hn1, b_xws, 1, Nn);

    // ======== attr_node_model layer 2 ========
    gather128_k<<<gridN_row, TB>>>(b_hn1, raw_rp, raw_col, b_aggN, nullptr, 0, Nn);
    gemm_k<<<gridN_gemm, 256>>>(b_hn1, HIDd, W_an2_s, b_aggN, HIDd, W_an2_n, b_hn2, Nn, 0);

    // ======== MixAttention projections ========
    gemm_k<<<gridN_gemm, 256>>>(b_hn2, HIDd, Wq, nullptr, 0, nullptr, b_q, Nn, 0);
    gemm_k<<<gridN_gemm, 256>>>(b_aggr_edge, HIDd, Wk, nullptr, 0, nullptr, b_k, Nn, 0);
    gemm_k<<<gridN_gemm, 256>>>(b_aggr_edge, HIDd, Wv, nullptr, 0, nullptr, b_v, Nn, 0);

    // ======== fused attention (score + softmax + weighted sum) ========
    attn_fused_k<<<gridN_row, TB>>>(b_q, b_k, b_v, raw_rp, raw_col, b_score, b_attn, Nn);

    // ======== classifier + log_softmax ========
    final_k<<<(Nn + 7) / 8, 256>>>(b_hn2, b_attn, W_out, out);
}